// round 4
// baseline (speedup 1.0000x reference)
#include <cuda_runtime.h>

#define HW    4096
#define BB    16
#define STEPS 409   // int(0.1 * 64 * 64)

typedef unsigned long long ull;
typedef unsigned int uint;

// cross-CTA coordination (zeroed in-kernel via generation handshake)
__device__ uint d_mask[STEPS];   // per-step solved bitmask across batches
__device__ uint d_prog[BB];      // per-batch completed-step counter
__device__ uint d_ready;         // monotone generation counter across launches

__device__ __forceinline__ uint rmax(uint v){uint d;asm("redux.sync.max.u32 %0, %1, 0xffffffff;":"=r"(d):"r"(v));return d;}
__device__ __forceinline__ uint rmin(uint v){uint d;asm("redux.sync.min.u32 %0, %1, 0xffffffff;":"=r"(d):"r"(v));return d;}

// f = 0.5*g + 0.5*h ; key = exp(-f * 0.125)
__device__ __forceinline__ float keyval(float g, float h){
    float f = __fadd_rn(__fmul_rn(0.5f, g), __fmul_rn(0.5f, h));
    return expf(__fmul_rn(-0.125f, f));
}
__device__ __forceinline__ ull packk(float k, int idx){
    return ((ull)__float_as_uint(k) << 32) | (ull)(uint)(0xFFFF - idx);
}
__device__ __forceinline__ ull umax64(ull a, ull b){ return a > b ? a : b; }
// second-of-3 given the winner (packs are unique per cell)
__device__ __forceinline__ ull sec3(ull a, ull b, ull c, ull w){
    ull x = (a == w) ? 0 : a, y = (b == w) ? 0 : b, z = (c == w) ? 0 : c;
    ull m = x > y ? x : y; return m > z ? m : z;
}
// idx-aware top-2 insert (handles relaxation of the current m/s holder cell)
__device__ __forceinline__ void ins2(ull &m, ull &s, ull v){
    if (!v) return;
    if ((((uint)v ^ (uint)m) & 0xFFFFu) == 0) { if (v > m) m = v; }
    else if (v > m) { s = m; m = v; }
    else if ((((uint)v ^ (uint)s) & 0xFFFFu) == 0) { if (v > s) s = v; }
    else if (v > s) s = v;
}

// ---- dynamic SMEM layout (bytes) ----
#define OFF_KEY    0        // float[4096]
#define OFF_GPAIR  16384    // float2[4096] {g, cost}; overlaid by pm/hist/path in finalize
#define OFF_HC     49152    // float[4096] heuristic+cost
#define OFF_STATE  65536    // uchar[4096]
#define OFF_ROWP   69632    // ull[64] per-row top1 (init handoff)
#define OFF_ROWS   70144    // ull[64] per-row top2 (init handoff)
#define OFF_SELLOG 70656    // u16[512]
#define OFF_UPDCNT 71680    // u8[512]
#define OFF_UPDCEL 72192    // u16[512*8]
#define OFF_MISC   80384    // int[0]=goal, int[1]=t_stop
#define SMEM_TOTAL 80448

__global__ void __launch_bounds__(512, 1)
astar_fused(const float* __restrict__ cost, const float* __restrict__ start,
            const float* __restrict__ goalm, const float* __restrict__ obst,
            float* __restrict__ out)
{
    extern __shared__ char smraw[];
    float*          s_key    = (float*)(smraw + OFF_KEY);
    float2*         s_gp     = (float2*)(smraw + OFF_GPAIR);
    float*          s_hc     = (float*)(smraw + OFF_HC);
    unsigned char*  s_state  = (unsigned char*)(smraw + OFF_STATE);
    ull*            s_rowp   = (ull*)(smraw + OFF_ROWP);
    ull*            s_rows   = (ull*)(smraw + OFF_ROWS);
    unsigned short* s_sellog = (unsigned short*)(smraw + OFF_SELLOG);
    unsigned char*  s_updcnt = (unsigned char*)(smraw + OFF_UPDCNT);
    unsigned short* s_updcel = (unsigned short*)(smraw + OFF_UPDCEL);
    int*            s_misc   = (int*)(smraw + OFF_MISC);

    const int b    = blockIdx.x;
    const int tid  = threadIdx.x;
    const int lane = tid & 31;
    const int warp = tid >> 5;

    const float* cb = cost  + b * HW;
    const float* sb = start + b * HW;
    const float* gb = goalm + b * HW;
    const float* ob = obst  + b * HW;

    // ---- zero this CTA's slice of coordination state + find goal ----
    {
        int s = b + tid * BB;
        if (s < STEPS) d_mask[s] = 0u;
        if (tid == 0) d_prog[b] = 0u;
    }
    {   // vectorized goal scan (one-hot)
        const float4* g4 = (const float4*)gb;
        for (int c = tid; c < HW / 4; c += 512) {
            float4 v = g4[c];
            if (v.x > 0.5f) s_misc[0] = 4 * c + 0;
            if (v.y > 0.5f) s_misc[0] = 4 * c + 1;
            if (v.z > 0.5f) s_misc[0] = 4 * c + 2;
            if (v.w > 0.5f) s_misc[0] = 4 * c + 3;
        }
    }
    __threadfence();
    __syncthreads();
    if (tid == 0) {
        uint old = atomicAdd(&d_ready, 1u);
        uint target = ((old >> 4) + 1u) << 4;   // 16 CTAs per run-generation
        while (*((volatile uint*)&d_ready) < target) {}
        __threadfence();
    }
    __syncthreads();

    const int goalIdx = s_misc[0];
    const int grow = goalIdx >> 6, gcol = goalIdx & 63;

    // ---- per-cell init ----
    for (int c = tid; c < HW; c += 512) {
        int r = c >> 6, col = c & 63;
        int di = abs(r - grow), dj = abs(col - gcol);
        int cheb = (di > dj) ? di : dj;                 // sum - min = max
        float euc = sqrtf((float)(di * di + dj * dj));
        float h = __fadd_rn((float)cheb, __fmul_rn(0.001f, euc));
        float cc = cb[c];
        h = __fadd_rn(h, cc);
        s_hc[c] = h;
        s_gp[c] = make_float2(0.0f, cc);
        unsigned char st = 0;
        if (ob[c] > 0.5f) st |= 4;
        bool open = (sb[c] > 0.5f);
        if (open) st |= 1;
        s_state[c] = st;
        s_key[c] = open ? keyval(0.0f, h) : 0.0f;
    }
    __syncthreads();

    // ---- build per-row top-2 packed maxima (16 warps x 4 rows) ----
    for (int k = 0; k < 4; k++) {
        int r = (warp << 2) + k, base = r << 6;
        ull p0 = packk(s_key[base + lane], base + lane);
        ull p1 = packk(s_key[base + 32 + lane], base + 32 + lane);
        ull q = umax64(p0, p1);
        uint hi = (uint)(q >> 32), M = rmax(hi);
        uint lo = (hi == M) ? (uint)q : 0u, L = rmax(lo);
        ull top = ((ull)M << 32) | L;
        if (p0 == top) p0 = 0;
        if (p1 == top) p1 = 0;
        ull q2 = umax64(p0, p1);
        uint hi2 = (uint)(q2 >> 32), M2 = rmax(hi2);
        uint lo2 = (hi2 == M2) ? (uint)q2 : 0u, L2 = rmax(lo2);
        if (lane == 0) { s_rowp[r] = top; s_rows[r] = ((ull)M2 << 32) | L2; }
    }
    __syncthreads();

    // ================= single-warp driver loop =================
    if (warp == 0) {
        const uint FULL = (1u << BB) - 1u;
        // lane l owns rows l (A) and l+32 (B): top1 rp*, top2 rs*
        ull rpA = s_rowp[lane], rpB = s_rowp[lane + 32];
        ull rsA = s_rows[lane], rsB = s_rows[lane + 32];

        // initial global top1 (top2 lazily refilled at step 0)
        ull gt1, gt2 = 0; bool gt2v = false;
        {
            ull q = umax64(rpA, rpB);
            uint hi = (uint)(q >> 32), M = rmax(hi);
            uint lo = (hi == M) ? (uint)q : 0u, L = rmax(lo);
            gt1 = ((ull)M << 32) | L;
        }

        int tfound = -1, scanpos = 0, step;
        for (step = 0; step < STEPS; ++step) {
            const int sel  = 0xFFFF - (int)((uint)gt1 & 0xFFFFu);   // known at cycle 0
            const int srow = sel >> 6, scol = sel & 63, rb = srow << 6;
            const bool solved = (sel == goalIdx);

            // ---- lazy top2 refill: 2 redux, independent of this step's work ----
            if (!gt2v) {
                ull a = rpA, c = rpB;
                if (lane == (srow & 31)) { if (srow < 32) a = rsA; else c = rsB; }
                ull q = umax64(a, c);
                uint hi = (uint)(q >> 32), M = rmax(hi);
                uint lo = (hi == M) ? (uint)q : 0u, L = rmax(lo);
                gt2 = ((ull)M << 32) | L;
            }

            float2 gp = s_gp[sel];
            float g2 = __fadd_rn(gp.x, gp.y);           // g[sel] + cost[sel]
            float k0 = s_key[rb + lane];                // pre-update row snapshot
            float k1 = s_key[rb + 32 + lane];

            // ---- neighbor evaluation (lanes 0-7) ----
            bool upd = false; int nb = 0; ull npack = 0;
            if (lane < 8) {
                int nidx = lane + (lane >= 4 ? 1 : 0);  // skip center
                int ni = srow + nidx / 3 - 1;
                int nj = scol + nidx % 3 - 1;
                if ((uint)ni < 64u && (uint)nj < 64u) {
                    nb = (ni << 6) | nj;
                    unsigned char st = s_state[nb];
                    if (st & 4u) {
                        bool open = st & 1u, closed = st & 2u;
                        float gn = s_gp[nb].x;
                        if ((!open && !closed) || (open && gn > g2)) upd = true;
                    }
                }
            }
            float nk = 0.0f;
            if (upd) {
                nk = keyval(g2, s_hc[nb]);
                npack = packk(nk, nb);
            }
            uint m8 = __ballot_sync(0xffffffffu, upd);   // convergence: snapshot reads done
            ull n0 = __shfl_sync(0xffffffffu, npack, 0);
            ull n1 = __shfl_sync(0xffffffffu, npack, 1);
            ull n2 = __shfl_sync(0xffffffffu, npack, 2);
            ull pL = __shfl_sync(0xffffffffu, npack, 3);
            ull pR = __shfl_sync(0xffffffffu, npack, 4);
            ull n5 = __shfl_sync(0xffffffffu, npack, 5);
            ull n6 = __shfl_sync(0xffffffffu, npack, 6);
            ull n7 = __shfl_sync(0xffffffffu, npack, 7);

            // ---- per-row update top-2 (all uniform ALU) ----
            ull up1 = umax64(umax64(n0, n1), n2);
            ull dn1 = umax64(umax64(n5, n6), n7);
            ull mid1 = umax64(pL, pR);
            ull up2 = sec3(n0, n1, n2, up1);
            ull dn2 = sec3(n5, n6, n7, dn1);
            ull mid2 = pL < pR ? pL : pR;
            ull bestn = umax64(umax64(up1, mid1), dn1);
            ull sbn = umax64(umax64((up1 == bestn) ? up2 : up1,
                                    (mid1 == bestn) ? mid2 : mid1),
                                    (dn1 == bestn) ? dn2 : dn1);

            // ---- global top-2 candidate merge ----
            ull oldg2 = gt2;
            ull cA = gt2, cBn = bestn, cC = sbn;
            if (bestn && (((uint)bestn ^ (uint)gt2) & 0xFFFFu) == 0) {
                cA = umax64(gt2, bestn); cBn = sbn; cC = 0;        // bestn relaxes gt2's cell
            } else if (sbn && (((uint)sbn ^ (uint)gt2) & 0xFFFFu) == 0) {
                cA = umax64(gt2, sbn); cC = 0;                     // sbn relaxes gt2's cell
            }
            ull cD = solved ? gt1 : 0;                             // sel stays open when solved
            ull mA = umax64(cA, cBn), wA = cA > cBn ? cBn : cA;
            ull mB = umax64(cC, cD),  wB = cC > cD  ? cD  : cC;
            ull c1 = umax64(mA, mB);
            ull c2 = umax64(mA > mB ? mB : mA, mA > mB ? wA : wB);
            gt1 = c1; gt2 = c2; gt2v = (c2 >= oldg2);

            // ---- row srow maintenance ----
            if (!solved) {
                // removal: exact rescan of row srow (off the critical path)
                ull p0 = packk(k0, rb + lane);
                ull p1 = packk(k1, rb + 32 + lane);
                if (scol < 32) { if (lane == scol) p0 = 0; }
                else           { if (lane == scol - 32) p1 = 0; }
                if (pL) { int c = scol - 1; if (c < 32) { if (lane == c && pL > p0) p0 = pL; }
                          else { if (lane == c - 32 && pL > p1) p1 = pL; } }
                if (pR) { int c = scol + 1; if (c < 32) { if (lane == c && pR > p0) p0 = pR; }
                          else { if (lane == c - 32 && pR > p1) p1 = pR; } }
                ull q = umax64(p0, p1);
                uint hi = (uint)(q >> 32), M = rmax(hi);
                uint lo = (hi == M) ? (uint)q : 0u, L = rmax(lo);
                ull rtop = ((ull)M << 32) | L;
                if (p0 == rtop) p0 = 0;
                if (p1 == rtop) p1 = 0;
                ull q2 = umax64(p0, p1);
                uint hi2 = (uint)(q2 >> 32), M2 = rmax(hi2);
                uint lo2 = (hi2 == M2) ? (uint)q2 : 0u, L2 = rmax(lo2);
                ull rsec = ((ull)M2 << 32) | L2;
                if (lane == (srow & 31)) {
                    if (srow < 32) { rpA = rtop; rsA = rsec; }
                    else           { rpB = rtop; rsB = rsec; }
                }
                if (lane == 0) {
                    s_key[sel] = 0.0f;
                    s_state[sel] = (unsigned char)((s_state[sel] & ~1u) | 2u);
                }
            } else {
                if (lane == (srow & 31)) {
                    if (srow < 32) { ins2(rpA, rsA, pL); ins2(rpA, rsA, pR); }
                    else           { ins2(rpB, rsB, pL); ins2(rpB, rsB, pR); }
                }
                if (lane == 0) {
                    s_state[sel] |= 2u;
                    atomicOr(&d_mask[step], 1u << b);
                }
            }
            // neighbor rows top-2 inserts
            if (srow > 0 && lane == ((srow - 1) & 31)) {
                if (srow - 1 < 32) { ins2(rpA, rsA, up1); ins2(rpA, rsA, up2); }
                else               { ins2(rpB, rsB, up1); ins2(rpB, rsB, up2); }
            }
            if (srow < 63 && lane == ((srow + 1) & 31)) {
                if (srow + 1 < 32) { ins2(rpA, rsA, dn1); ins2(rpA, rsA, dn2); }
                else               { ins2(rpB, rsB, dn1); ins2(rpB, rsB, dn2); }
            }

            // ---- apply neighbor updates to SMEM state ----
            if (upd) {
                s_key[nb] = nk;
                s_gp[nb].x = g2;
                s_state[nb] |= 1u;
                int pos = __popc(m8 & ((1u << lane) - 1u));
                s_updcel[step * 8 + pos] = (unsigned short)nb;
            }
            if (lane == 0) {
                s_sellog[step] = (unsigned short)sel;
                s_updcnt[step] = (unsigned char)__popc(m8);
            }

            // ---- periodic progress publish + opportunistic t_stop detection ----
            if (((step & 7) == 7) && lane == 0) {
                __threadfence();
                *((volatile uint*)&d_prog[b]) = (uint)(step + 1);
            }
            if (((step & 15) == 15) && tfound < 0) {
                uint pv = (lane < BB) ? ((volatile uint*)d_prog)[lane] : 0xffffffffu;
                uint mn = rmin(pv);
                while (scanpos < (int)mn) {
                    int idx = scanpos + lane;
                    uint mv = (idx < (int)mn) ? ((volatile uint*)d_mask)[idx] : 0u;
                    uint bal = __ballot_sync(0xffffffffu, mv == FULL);
                    if (bal) { tfound = scanpos + __ffs(bal) - 1; break; }
                    scanpos += 32; if (scanpos > (int)mn) scanpos = (int)mn;
                }
            }
            __syncwarp();                               // cross-lane SMEM visibility
            if (tfound >= 0 && step >= tfound) { step++; break; }
        }

        // final progress publish (guarantees other CTAs' t_stop spin terminates)
        if (lane == 0) {
            __threadfence();
            *((volatile uint*)&d_prog[b]) = (uint)step;
        }

        // ---- resolve global t_stop ----
        int ts = tfound;
        if (ts < 0) {
            while (true) {
                uint pv = (lane < BB) ? ((volatile uint*)d_prog)[lane] : 0xffffffffu;
                uint mn = rmin(pv);
                bool fnd = false;
                while (scanpos < (int)mn) {
                    int idx = scanpos + lane;
                    uint mv = (idx < (int)mn) ? ((volatile uint*)d_mask)[idx] : 0u;
                    uint bal = __ballot_sync(0xffffffffu, mv == FULL);
                    if (bal) { ts = scanpos + __ffs(bal) - 1; fnd = true; break; }
                    scanpos += 32; if (scanpos > (int)mn) scanpos = (int)mn;
                }
                if (fnd) break;
                if (mn >= (uint)STEPS) { ts = STEPS - 1; break; }
            }
        }
        if (lane == 0) s_misc[1] = ts;
    }
    __syncthreads();   // idle warps sleep here during the loop

    // ================= finalize (all 512 threads, SMEM logs) =================
    uint*          pm   = (uint*)(smraw + OFF_GPAIR);            // overlay, 16KB
    unsigned char* hist = (unsigned char*)(smraw + OFF_GPAIR + 16384);
    unsigned char* path = (unsigned char*)(smraw + OFF_GPAIR + 20480);

    for (int c = tid; c < HW; c += 512) { pm[c] = 0u; hist[c] = 0; path[c] = 0; }
    __syncthreads();

    const int ts = s_misc[1];
    for (int s = tid; s <= ts; s += 512) {
        int sl = s_sellog[s];
        hist[sl] = 1;
        int cnt = s_updcnt[s];
        uint packed = ((uint)(s + 1) << 12) | (uint)sl;          // last-writer wins
        for (int k = 0; k < cnt; k++)
            atomicMax(&pm[s_updcel[s * 8 + k]], packed);
    }
    __syncthreads();

    if (tid == 0) {
        path[goalIdx] = 1;
        uint pv = pm[goalIdx];
        int loc = pv ? (int)(pv & 4095u) : goalIdx;
        for (int i = 0; i < ts; i++) {
            if (path[loc]) break;    // deterministic chase: revisit => future marks redundant
            path[loc] = 1;
            uint q = pm[loc];
            loc = q ? (int)(q & 4095u) : goalIdx;
        }
    }
    __syncthreads();

    for (int c = tid; c < HW; c += 512) {
        out[b * HW + c]           = hist[c] ? 1.0f : 0.0f;   // hist (B,1,64,64)
        out[BB * HW + b * HW + c] = path[c] ? 1.0f : 0.0f;   // path_maps (B,1,64,64)
    }
}

// ---------------- launch -------------------------------------------------
extern "C" void kernel_launch(void* const* d_in, const int* in_sizes, int n_in,
                              void* d_out, int out_size) {
    const float* cost  = (const float*)d_in[0];
    const float* start = (const float*)d_in[1];
    const float* goal  = (const float*)d_in[2];
    const float* obst  = (const float*)d_in[3];
    float* out = (float*)d_out;

    cudaFuncSetAttribute(astar_fused, cudaFuncAttributeMaxDynamicSharedMemorySize, SMEM_TOTAL);
    astar_fused<<<BB, 512, SMEM_TOTAL>>>(cost, start, goal, obst, out);
}

// round 5
// speedup vs baseline: 1.1887x; 1.1887x over previous
#include <cuda_runtime.h>

#define HW    4096
#define BB    16
#define STEPS 409   // int(0.1 * 64 * 64)

typedef unsigned long long ull;
typedef unsigned int uint;

// cross-CTA coordination (zeroed in-kernel via generation handshake)
__device__ uint d_mask[STEPS];   // per-step solved bitmask across batches
__device__ uint d_prog[BB];      // per-batch completed-step counter
__device__ uint d_ready;         // monotone generation counter across launches

__device__ __forceinline__ uint rmax(uint v){uint d;asm("redux.sync.max.u32 %0, %1, 0xffffffff;":"=r"(d):"r"(v));return d;}
__device__ __forceinline__ uint rmin(uint v){uint d;asm("redux.sync.min.u32 %0, %1, 0xffffffff;":"=r"(d):"r"(v));return d;}

// f = 0.5*g + 0.5*h ; key = exp(-f * 0.125)
__device__ __forceinline__ float keyval(float g, float h){
    float f = __fadd_rn(__fmul_rn(0.5f, g), __fmul_rn(0.5f, h));
    return expf(__fmul_rn(-0.125f, f));
}
__device__ __forceinline__ ull packk(float k, int idx){
    return ((ull)__float_as_uint(k) << 32) | (ull)(uint)(0xFFFF - idx);
}
__device__ __forceinline__ ull umax64(ull a, ull b){ return a > b ? a : b; }

// ---- dynamic SMEM layout (bytes) ----
#define OFF_KEY    0        // float[4096]
#define OFF_GPAIR  16384    // float2[4096] {g, cost}; overlaid by pm/hist/path in finalize
#define OFF_HC     49152    // float[4096] heuristic+cost
#define OFF_STATE  65536    // uchar[4096] bit0 open, bit1 closed, bit2 free
#define OFF_ROWP   69632    // ull[64] per-row packed max (init handoff)
#define OFF_SELLOG 70144    // u16[512]
#define OFF_UPDCNT 71168    // u8[512]
#define OFF_UPDCEL 71680    // u16[512*8]
#define OFF_MISC   79872    // int[0]=goal, int[1]=t_stop
#define SMEM_TOTAL 79936

__global__ void __launch_bounds__(512, 1)
astar_fused(const float* __restrict__ cost, const float* __restrict__ start,
            const float* __restrict__ goalm, const float* __restrict__ obst,
            float* __restrict__ out)
{
    extern __shared__ char smraw[];
    float*          s_key    = (float*)(smraw + OFF_KEY);
    float2*         s_gp     = (float2*)(smraw + OFF_GPAIR);
    float*          s_hc     = (float*)(smraw + OFF_HC);
    unsigned char*  s_state  = (unsigned char*)(smraw + OFF_STATE);
    ull*            s_rowp   = (ull*)(smraw + OFF_ROWP);
    unsigned short* s_sellog = (unsigned short*)(smraw + OFF_SELLOG);
    unsigned char*  s_updcnt = (unsigned char*)(smraw + OFF_UPDCNT);
    unsigned short* s_updcel = (unsigned short*)(smraw + OFF_UPDCEL);
    int*            s_misc   = (int*)(smraw + OFF_MISC);

    const int b    = blockIdx.x;
    const int tid  = threadIdx.x;
    const int lane = tid & 31;
    const int warp = tid >> 5;

    const float* cb = cost  + b * HW;
    const float* sb = start + b * HW;
    const float* gb = goalm + b * HW;
    const float* ob = obst  + b * HW;

    // ---- zero this CTA's slice of coordination state + find goal ----
    {
        int s = b + tid * BB;
        if (s < STEPS) d_mask[s] = 0u;
        if (tid == 0) d_prog[b] = 0u;
    }
    {   // vectorized goal scan (one-hot)
        const float4* g4 = (const float4*)gb;
        for (int c = tid; c < HW / 4; c += 512) {
            float4 v = g4[c];
            if (v.x > 0.5f) s_misc[0] = 4 * c + 0;
            if (v.y > 0.5f) s_misc[0] = 4 * c + 1;
            if (v.z > 0.5f) s_misc[0] = 4 * c + 2;
            if (v.w > 0.5f) s_misc[0] = 4 * c + 3;
        }
    }
    __threadfence();
    __syncthreads();
    if (tid == 0) {
        uint old = atomicAdd(&d_ready, 1u);
        uint target = ((old >> 4) + 1u) << 4;   // 16 CTAs per run-generation
        while (*((volatile uint*)&d_ready) < target) {}
        __threadfence();
    }
    __syncthreads();

    const int goalIdx = s_misc[0];
    const int grow = goalIdx >> 6, gcol = goalIdx & 63;

    // ---- per-cell init ----
    for (int c = tid; c < HW; c += 512) {
        int r = c >> 6, col = c & 63;
        int di = abs(r - grow), dj = abs(col - gcol);
        int cheb = (di > dj) ? di : dj;                 // sum - min = max
        float euc = sqrtf((float)(di * di + dj * dj));
        float h = __fadd_rn((float)cheb, __fmul_rn(0.001f, euc));
        float cc = cb[c];
        h = __fadd_rn(h, cc);
        s_hc[c] = h;
        s_gp[c] = make_float2(0.0f, cc);
        unsigned char st = 0;
        if (ob[c] > 0.5f) st |= 4;
        bool open = (sb[c] > 0.5f);
        if (open) st |= 1;
        s_state[c] = st;
        s_key[c] = open ? keyval(0.0f, h) : 0.0f;
    }
    __syncthreads();

    // ---- build per-row packed maxima (16 warps x 4 rows) ----
    for (int k = 0; k < 4; k++) {
        int r = (warp << 2) + k, base = r << 6;
        ull q0 = packk(s_key[base + lane], base + lane);
        ull q1 = packk(s_key[base + 32 + lane], base + 32 + lane);
        ull q = umax64(q0, q1);
        uint hi = (uint)(q >> 32), M = rmax(hi);
        uint lo = (hi == M) ? (uint)q : 0u, L = rmax(lo);
        if (lane == 0) s_rowp[r] = ((ull)M << 32) | L;
    }
    __syncthreads();

    // ================= single-warp driver loop =================
    if (warp == 0) {
        const uint FULL = (1u << BB) - 1u;
        // lane l owns rows l (rpA) and l+32 (rpB)
        ull rpA = s_rowp[lane], rpB = s_rowp[lane + 32];
        // carried row state: cp0/cp1 = per-lane partials of row `crow` (rp[crow] stale)
        ull cp0 = 0, cp1 = 0;
        int crow = -1;

        int tfound = -1, scanpos = 0, step;
        for (step = 0; step < STEPS; ++step) {
            // ---- fused global argmax: rows via rp (carried row masked) + carried partials ----
            ull a = rpA, c = rpB;
            if (crow >= 0 && lane == (crow & 31)) { if (crow < 32) a = 0; else c = 0; }
            ull q = umax64(umax64(a, c), umax64(cp0, cp1));
            uint hi = (uint)(q >> 32), M = rmax(hi);
            uint lo = (hi == M) ? (uint)q : 0u, L = rmax(lo);
            int sel  = 0xFFFF - (int)(L & 0xFFFFu);
            int srow = sel >> 6, scol = sel & 63, rb = srow << 6;
            bool solved = (sel == goalIdx);

            // ---- sel + row snapshot loads ----
            float2 gp = s_gp[sel];
            float g2 = __fadd_rn(gp.x, gp.y);           // g[sel] + cost[sel]
            float k0 = s_key[rb + lane];
            float k1 = s_key[rb + 32 + lane];

            // ---- fold previous carried row (result needed only next step) ----
            // skip only when the carry is being re-created for the same row
            bool dofold = (crow >= 0) && (solved || crow != srow);
            ull foldres = 0;
            if (dofold) {
                ull fq = umax64(cp0, cp1);
                uint fh = (uint)(fq >> 32), FM = rmax(fh);
                uint fl = (fh == FM) ? (uint)fq : 0u, FL = rmax(fl);
                foldres = ((ull)FM << 32) | FL;
            }

            // ---- neighbor evaluation (lanes 0-7) ----
            bool upd = false; int nb = 0; float nk = 0.0f; uint nkb = 0u;
            if (lane < 8) {
                int nidx = lane + (lane >= 4 ? 1 : 0);  // skip center
                int ni = srow + nidx / 3 - 1;
                int nj = scol + nidx % 3 - 1;
                if ((uint)ni < 64u && (uint)nj < 64u) {
                    nb = (ni << 6) | nj;
                    unsigned char st = s_state[nb];
                    if (st & 4u) {
                        bool open = st & 1u, closed = st & 2u;
                        float gn = s_gp[nb].x;
                        if ((!open && !closed) || (open && gn > g2)) upd = true;
                    }
                }
            }
            if (upd) { nk = keyval(g2, s_hc[nb]); nkb = __float_as_uint(nk); }
            uint m8 = __ballot_sync(0xffffffffu, upd);   // convergence: snapshot reads done

            // ---- broadcast key bits only (8x 32-bit shfl); indices derived from sel ----
            uint h0 = __shfl_sync(0xffffffffu, nkb, 0);
            uint h1 = __shfl_sync(0xffffffffu, nkb, 1);
            uint h2 = __shfl_sync(0xffffffffu, nkb, 2);
            uint h3 = __shfl_sync(0xffffffffu, nkb, 3);
            uint h4 = __shfl_sync(0xffffffffu, nkb, 4);
            uint h5 = __shfl_sync(0xffffffffu, nkb, 5);
            uint h6 = __shfl_sync(0xffffffffu, nkb, 6);
            uint h7 = __shfl_sync(0xffffffffu, nkb, 7);
            int iU = rb - 64, iD = rb + 64;
            ull n0 = (m8 & 1u)  ? (((ull)h0 << 32) | (uint)(0xFFFF - (iU + scol - 1))) : 0;
            ull n1 = (m8 & 2u)  ? (((ull)h1 << 32) | (uint)(0xFFFF - (iU + scol    ))) : 0;
            ull n2 = (m8 & 4u)  ? (((ull)h2 << 32) | (uint)(0xFFFF - (iU + scol + 1))) : 0;
            ull pL = (m8 & 8u)  ? (((ull)h3 << 32) | (uint)(0xFFFF - (rb + scol - 1))) : 0;
            ull pR = (m8 & 16u) ? (((ull)h4 << 32) | (uint)(0xFFFF - (rb + scol + 1))) : 0;
            ull n5 = (m8 & 32u) ? (((ull)h5 << 32) | (uint)(0xFFFF - (iD + scol - 1))) : 0;
            ull n6 = (m8 & 64u) ? (((ull)h6 << 32) | (uint)(0xFFFF - (iD + scol    ))) : 0;
            ull n7 = (m8 & 128u)? (((ull)h7 << 32) | (uint)(0xFFFF - (iD + scol + 1))) : 0;
            ull up1  = umax64(umax64(n0, n1), n2);       // row srow-1 increase
            ull mid1 = umax64(pL, pR);                   // row srow   increase
            ull dn1  = umax64(umax64(n5, n6), n7);       // row srow+1 increase

            // ---- new carry partials for row srow (removal + same-row substitution) ----
            ull ncp0 = 0, ncp1 = 0;
            if (!solved) {
                ncp0 = packk(k0, rb + lane);
                ncp1 = packk(k1, rb + 32 + lane);
                if (scol < 32) { if (lane == scol) ncp0 = 0; }
                else           { if (lane == scol - 32) ncp1 = 0; }
                if (pL) { int cc = scol - 1;
                    if (cc < 32) { if (lane == cc && pL > ncp0) ncp0 = pL; }
                    else         { if (lane == cc - 32 && pL > ncp1) ncp1 = pL; } }
                if (pR) { int cc = scol + 1;
                    if (cc < 32) { if (lane == cc && pR > ncp0) ncp0 = pR; }
                    else         { if (lane == cc - 32 && pR > ncp1) ncp1 = pR; } }
            }

            // ---- rp updates (fold write first, then merges) ----
            if (dofold) {
                ull val = foldres;
                if (crow == srow) val = umax64(val, mid1);   // only possible when solved
                if (lane == (crow & 31)) { if (crow < 32) rpA = val; else rpB = val; }
            }
            if (solved && crow != srow) {
                if (lane == (srow & 31)) {
                    if (srow < 32) rpA = umax64(rpA, mid1); else rpB = umax64(rpB, mid1);
                }
            }
            if (srow > 0 && up1) {
                int r = srow - 1;
                if (lane == (r & 31)) { if (r < 32) rpA = umax64(rpA, up1); else rpB = umax64(rpB, up1); }
            }
            if (srow < 63 && dn1) {
                int r = srow + 1;
                if (lane == (r & 31)) { if (r < 32) rpA = umax64(rpA, dn1); else rpB = umax64(rpB, dn1); }
            }
            // carry handoff
            if (!solved) { crow = srow; cp0 = ncp0; cp1 = ncp1; }
            else         { crow = -1;   cp0 = 0;    cp1 = 0;    }

            // ---- apply updates to SMEM state ----
            if (upd) {
                s_key[nb] = nk;
                s_gp[nb].x = g2;
                s_state[nb] |= 1u;
                int pos = __popc(m8 & ((1u << lane) - 1u));
                s_updcel[step * 8 + pos] = (unsigned short)nb;
            }
            if (lane == 0) {
                if (!solved) {
                    s_key[sel] = 0.0f;
                    s_state[sel] = (unsigned char)((s_state[sel] & ~1u) | 2u);
                } else {
                    s_state[sel] |= 2u;
                    atomicOr(&d_mask[step], 1u << b);
                }
                s_sellog[step] = (unsigned short)sel;
                s_updcnt[step] = (unsigned char)__popc(m8);
            }

            // ---- periodic progress publish + opportunistic t_stop detection ----
            if (((step & 7) == 7) && lane == 0) {
                __threadfence();
                *((volatile uint*)&d_prog[b]) = (uint)(step + 1);
            }
            if (((step & 15) == 15) && tfound < 0) {
                uint pv = (lane < BB) ? ((volatile uint*)d_prog)[lane] : 0xffffffffu;
                uint mn = rmin(pv);
                while (scanpos < (int)mn) {
                    int idx = scanpos + lane;
                    uint mv = (idx < (int)mn) ? ((volatile uint*)d_mask)[idx] : 0u;
                    uint bal = __ballot_sync(0xffffffffu, mv == FULL);
                    if (bal) { tfound = scanpos + __ffs(bal) - 1; break; }
                    scanpos += 32; if (scanpos > (int)mn) scanpos = (int)mn;
                }
            }
            __syncwarp();                               // cross-lane SMEM visibility
            if (tfound >= 0 && step >= tfound) { step++; break; }
        }

        // final progress publish (guarantees other CTAs' t_stop spin terminates)
        if (lane == 0) {
            __threadfence();
            *((volatile uint*)&d_prog[b]) = (uint)step;
        }

        // ---- resolve global t_stop ----
        int ts = tfound;
        if (ts < 0) {
            while (true) {
                uint pv = (lane < BB) ? ((volatile uint*)d_prog)[lane] : 0xffffffffu;
                uint mn = rmin(pv);
                bool fnd = false;
                while (scanpos < (int)mn) {
                    int idx = scanpos + lane;
                    uint mv = (idx < (int)mn) ? ((volatile uint*)d_mask)[idx] : 0u;
                    uint bal = __ballot_sync(0xffffffffu, mv == FULL);
                    if (bal) { ts = scanpos + __ffs(bal) - 1; fnd = true; break; }
                    scanpos += 32; if (scanpos > (int)mn) scanpos = (int)mn;
                }
                if (fnd) break;
                if (mn >= (uint)STEPS) { ts = STEPS - 1; break; }
            }
        }
        if (lane == 0) s_misc[1] = ts;
    }
    __syncthreads();   // idle warps sleep here during the loop

    // ================= finalize (all 512 threads, SMEM logs) =================
    uint*          pm   = (uint*)(smraw + OFF_GPAIR);            // overlay, 16KB
    unsigned char* hist = (unsigned char*)(smraw + OFF_GPAIR + 16384);
    unsigned char* path = (unsigned char*)(smraw + OFF_GPAIR + 20480);

    for (int c = tid; c < HW; c += 512) { pm[c] = 0u; hist[c] = 0; path[c] = 0; }
    __syncthreads();

    const int ts = s_misc[1];
    for (int s = tid; s <= ts; s += 512) {
        int sl = s_sellog[s];
        hist[sl] = 1;
        int cnt = s_updcnt[s];
        uint packed = ((uint)(s + 1) << 12) | (uint)sl;          // last-writer wins
        for (int k = 0; k < cnt; k++)
            atomicMax(&pm[s_updcel[s * 8 + k]], packed);
    }
    __syncthreads();

    if (tid == 0) {
        path[goalIdx] = 1;
        uint pv = pm[goalIdx];
        int loc = pv ? (int)(pv & 4095u) : goalIdx;
        for (int i = 0; i < ts; i++) {
            if (path[loc]) break;    // deterministic chase: revisit => future marks redundant
            path[loc] = 1;
            uint q = pm[loc];
            loc = q ? (int)(q & 4095u) : goalIdx;
        }
    }
    __syncthreads();

    for (int c = tid; c < HW; c += 512) {
        out[b * HW + c]           = hist[c] ? 1.0f : 0.0f;   // hist (B,1,64,64)
        out[BB * HW + b * HW + c] = path[c] ? 1.0f : 0.0f;   // path_maps (B,1,64,64)
    }
}

// ---------------- launch -------------------------------------------------
extern "C" void kernel_launch(void* const* d_in, const int* in_sizes, int n_in,
                              void* d_out, int out_size) {
    const float* cost  = (const float*)d_in[0];
    const float* start = (const float*)d_in[1];
    const float* goal  = (const float*)d_in[2];
    const float* obst  = (const float*)d_in[3];
    float* out = (float*)d_out;

    cudaFuncSetAttribute(astar_fused, cudaFuncAttributeMaxDynamicSharedMemorySize, SMEM_TOTAL);
    astar_fused<<<BB, 512, SMEM_TOTAL>>>(cost, start, goal, obst, out);
}

// round 6
// speedup vs baseline: 1.3750x; 1.1567x over previous
#include <cuda_runtime.h>

#define HW    4096
#define BB    16
#define STEPS 409   // int(0.1 * 64 * 64)

typedef unsigned long long ull;
typedef unsigned int uint;

#define SENT 0xFFFFFFFFFFFFFFFFull
#define FINF __int_as_float(0x7F800000)

// cross-CTA coordination (zeroed in-kernel via generation handshake)
__device__ uint d_mask[STEPS];   // per-step solved bitmask across batches
__device__ uint d_prog[BB];      // per-batch completed-step counter
__device__ uint d_ready;         // monotone generation counter across launches

__device__ __forceinline__ uint rmin(uint v){uint d;asm volatile("redux.sync.min.u32 %0, %1, 0xffffffff;":"=r"(d):"r"(v):"memory");return d;}

__device__ __forceinline__ ull packf(float f, int idx){
    return ((ull)__float_as_uint(f) << 32) | (ull)(uint)idx;
}
__device__ __forceinline__ ull umin64(ull a, ull b){ return a < b ? a : b; }

// ---- dynamic SMEM layout (bytes) ----
#define OFF_F      0        // float[4096]: f = 0.5g+0.5(h+cost); +INF when not open
#define OFF_GPAIR  16384    // float2[4096] {g, cost}; overlaid by pm/hist/path in finalize
#define OFF_HC     49152    // float[4096] heuristic+cost
#define OFF_STATE  65536    // uchar[4096] bit0 open, bit1 closed, bit2 free
#define OFF_ROWP   69632    // ull[64] per-row packed min (init handoff)
#define OFF_SELLOG 70144    // u16[512]
#define OFF_UPDCNT 71168    // u8[512]
#define OFF_UPDCEL 71680    // u16[512*8]
#define OFF_MISC   79872    // int[0]=goal, int[1]=t_stop
#define SMEM_TOTAL 79936

__global__ void __launch_bounds__(512, 1)
astar_fused(const float* __restrict__ cost, const float* __restrict__ start,
            const float* __restrict__ goalm, const float* __restrict__ obst,
            float* __restrict__ out)
{
    extern __shared__ char smraw[];
    float*          s_f      = (float*)(smraw + OFF_F);
    float2*         s_gp     = (float2*)(smraw + OFF_GPAIR);
    float*          s_hc     = (float*)(smraw + OFF_HC);
    unsigned char*  s_state  = (unsigned char*)(smraw + OFF_STATE);
    ull*            s_rowp   = (ull*)(smraw + OFF_ROWP);
    unsigned short* s_sellog = (unsigned short*)(smraw + OFF_SELLOG);
    unsigned char*  s_updcnt = (unsigned char*)(smraw + OFF_UPDCNT);
    unsigned short* s_updcel = (unsigned short*)(smraw + OFF_UPDCEL);
    int*            s_misc   = (int*)(smraw + OFF_MISC);

    const int b    = blockIdx.x;
    const int tid  = threadIdx.x;
    const int lane = tid & 31;
    const int warp = tid >> 5;

    const float* cb = cost  + b * HW;
    const float* sb = start + b * HW;
    const float* gb = goalm + b * HW;
    const float* ob = obst  + b * HW;

    // ---- zero this CTA's slice of coordination state + find goal ----
    {
        int s = b + tid * BB;
        if (s < STEPS) d_mask[s] = 0u;
        if (tid == 0) d_prog[b] = 0u;
    }
    {   // vectorized goal scan (one-hot)
        const float4* g4 = (const float4*)gb;
        for (int c = tid; c < HW / 4; c += 512) {
            float4 v = g4[c];
            if (v.x > 0.5f) s_misc[0] = 4 * c + 0;
            if (v.y > 0.5f) s_misc[0] = 4 * c + 1;
            if (v.z > 0.5f) s_misc[0] = 4 * c + 2;
            if (v.w > 0.5f) s_misc[0] = 4 * c + 3;
        }
    }
    __threadfence();
    __syncthreads();
    if (tid == 0) {
        uint old = atomicAdd(&d_ready, 1u);
        uint target = ((old >> 4) + 1u) << 4;   // 16 CTAs per run-generation
        while (*((volatile uint*)&d_ready) < target) {}
        __threadfence();
    }
    __syncthreads();

    const int goalIdx = s_misc[0];
    const int grow = goalIdx >> 6, gcol = goalIdx & 63;

    // ---- per-cell init ----
    for (int c = tid; c < HW; c += 512) {
        int r = c >> 6, col = c & 63;
        int di = abs(r - grow), dj = abs(col - gcol);
        int cheb = (di > dj) ? di : dj;                 // sum - min = max
        float euc = sqrtf((float)(di * di + dj * dj));
        float h = __fadd_rn((float)cheb, __fmul_rn(0.001f, euc));
        float cc = cb[c];
        h = __fadd_rn(h, cc);                            // h_total = heuristic + cost
        s_hc[c] = h;
        s_gp[c] = make_float2(0.0f, cc);
        unsigned char st = 0;
        if (ob[c] > 0.5f) st |= 4;
        bool open = (sb[c] > 0.5f);
        if (open) st |= 1;
        s_state[c] = st;
        s_f[c] = open ? __fmul_rn(0.5f, h) : FINF;       // f = 0.5*0 + 0.5*h
    }
    __syncthreads();

    // ---- build per-row packed minima (16 warps x 4 rows) ----
    for (int k = 0; k < 4; k++) {
        int r = (warp << 2) + k, base = r << 6;
        ull q0 = packf(s_f[base + lane], base + lane);
        ull q1 = packf(s_f[base + 32 + lane], base + 32 + lane);
        ull q = umin64(q0, q1);
        uint hi = (uint)(q >> 32), M = rmin(hi);
        uint lo = (hi == M) ? (uint)q : 0xFFFFFFFFu, L = rmin(lo);
        if (lane == 0) s_rowp[r] = ((ull)M << 32) | L;
    }
    __syncthreads();

    // ================= single-warp driver loop =================
    if (warp == 0) {
        const uint FULL = (1u << BB) - 1u;
        // lane l owns rows l (rpA) and l+32 (rpB)
        ull rpA = s_rowp[lane], rpB = s_rowp[lane + 32];

        int tfound = -1, scanpos = 0, step;
        uint pv_pref = 0xffffffffu, mv_pref = 0u;

        for (step = 0; step < STEPS; ++step) {
            // ---- global argmin from register row minima (tie: smallest idx) ----
            ull p = umin64(rpA, rpB);
            uint hi = (uint)(p >> 32);
            uint M = rmin(hi);
            uint lo = (hi == M) ? (uint)p : 0xFFFFFFFFu;
            uint L = rmin(lo);
            int sel  = (int)(L & 0xFFFFu);
            int srow = sel >> 6, scol = sel & 63, rb = srow << 6;
            bool solved = (sel == goalIdx);

            float2 gp = s_gp[sel];
            float g2 = __fadd_rn(gp.x, gp.y);           // g[sel] + cost[sel]
            float k0 = s_f[rb + lane];                  // pre-update row snapshot
            float k1 = s_f[rb + 32 + lane];

            // ---- neighbor evaluation (lanes 0-7) ----
            bool upd = false; int nb = 0; float nf = 0.0f; ull npack = SENT;
            if (lane < 8) {
                int nidx = lane + (lane >= 4 ? 1 : 0);  // skip center
                int ni = srow + nidx / 3 - 1;
                int nj = scol + nidx % 3 - 1;
                if ((uint)ni < 64u && (uint)nj < 64u) {
                    nb = (ni << 6) | nj;
                    unsigned char st = s_state[nb];
                    if (st & 4u) {
                        bool open = st & 1u, closed = st & 2u;
                        float gn = s_gp[nb].x;
                        if ((!open && !closed) || (open && gn > g2)) upd = true;
                    }
                }
            }
            if (upd) {
                nf = __fmul_rn(0.5f, __fadd_rn(g2, s_hc[nb]));  // == 0.5*g2 + 0.5*h
                npack = packf(nf, nb);
            }
            uint m8 = __ballot_sync(0xffffffffu, upd);   // convergence: snapshot reads done
            ull n0 = __shfl_sync(0xffffffffu, npack, 0);
            ull n1 = __shfl_sync(0xffffffffu, npack, 1);
            ull n2 = __shfl_sync(0xffffffffu, npack, 2);
            ull pL = __shfl_sync(0xffffffffu, npack, 3);
            ull pR = __shfl_sync(0xffffffffu, npack, 4);
            ull n5 = __shfl_sync(0xffffffffu, npack, 5);
            ull n6 = __shfl_sync(0xffffffffu, npack, 6);
            ull n7 = __shfl_sync(0xffffffffu, npack, 7);
            ull up1  = umin64(umin64(n0, n1), n2);       // row srow-1 decrease
            ull mid1 = umin64(pL, pR);                   // row srow   decrease
            ull dn1  = umin64(umin64(n5, n6), n7);       // row srow+1 decrease

            ull newrow;   // new packed min of row srow (warp-uniform)
            if (!solved) {
                // removal: rescan row snapshot, substituting same-row decreases
                ull p0 = packf(k0, rb + lane);
                ull p1 = packf(k1, rb + 32 + lane);
                if (scol < 32) { if (lane == scol) p0 = SENT; }
                else           { if (lane == scol - 32) p1 = SENT; }
                if (pL != SENT) { int c = scol - 1;
                    if (c < 32) { if (lane == c) p0 = umin64(p0, pL); }
                    else        { if (lane == c - 32) p1 = umin64(p1, pL); } }
                if (pR != SENT) { int c = scol + 1;
                    if (c < 32) { if (lane == c) p0 = umin64(p0, pR); }
                    else        { if (lane == c - 32) p1 = umin64(p1, pR); } }
                ull pp = p0 < p1 ? p0 : p1;
                uint h2 = (uint)(pp >> 32);
                uint mm = rmin(h2);
                uint l2 = (h2 == mm) ? (uint)pp : 0xFFFFFFFFu;
                uint lm2 = rmin(l2);
                newrow = ((ull)mm << 32) | lm2;
                if (lane == 0) {
                    s_f[sel] = FINF;
                    s_state[sel] = (unsigned char)((s_state[sel] & ~1u) | 2u);
                }
            } else {
                ull cur = (srow < 32) ? __shfl_sync(0xffffffffu, rpA, srow)
                                      : __shfl_sync(0xffffffffu, rpB, srow - 32);
                newrow = umin64(cur, mid1);
                if (lane == 0) {
                    s_state[sel] |= 2u;
                    atomicOr(&d_mask[step], 1u << b);
                }
            }

            // ---- merge updated rows into register row minima ----
            if (lane == (srow & 31)) { if (srow < 32) rpA = newrow; else rpB = newrow; }
            if (srow > 0  && lane == ((srow - 1) & 31)) {
                if (srow - 1 < 32) rpA = umin64(rpA, up1); else rpB = umin64(rpB, up1);
            }
            if (srow < 63 && lane == ((srow + 1) & 31)) {
                if (srow + 1 < 32) rpA = umin64(rpA, dn1); else rpB = umin64(rpB, dn1);
            }

            // ---- apply neighbor updates to SMEM state ----
            if (upd) {
                s_f[nb] = nf;
                s_gp[nb].x = g2;
                s_state[nb] |= 1u;
                int pos = __popc(m8 & ((1u << lane) - 1u));
                s_updcel[step * 8 + pos] = (unsigned short)nb;
            }
            if (lane == 0) {
                s_sellog[step] = (unsigned short)sel;
                s_updcnt[step] = (unsigned char)__popc(m8);
            }

            // ---- periodic progress publish + prefetched t_stop detection ----
            if (((step & 7) == 7) && lane == 0) {
                __threadfence();
                *((volatile uint*)&d_prog[b]) = (uint)(step + 1);
            }
            if (((step & 15) == 14) && tfound < 0) {
                pv_pref = (lane < BB) ? *((volatile uint*)&d_prog[lane]) : 0xffffffffu;
                int idx = scanpos + lane;
                mv_pref = (idx < STEPS) ? *((volatile uint*)&d_mask[idx]) : 0u;
            }
            if (((step & 15) == 15) && tfound < 0) {
                uint mn = rmin(pv_pref);
                bool first = true;
                while (scanpos < (int)mn) {
                    int idx = scanpos + lane;
                    uint mv;
                    if (first) { mv = (idx < (int)mn) ? mv_pref : 0u; first = false; }
                    else       { mv = (idx < (int)mn) ? *((volatile uint*)&d_mask[idx]) : 0u; }
                    uint bal = __ballot_sync(0xffffffffu, mv == FULL);
                    if (bal) { tfound = scanpos + __ffs(bal) - 1; break; }
                    scanpos += 32; if (scanpos > (int)mn) scanpos = (int)mn;
                }
            }
            if (tfound >= 0 && step >= tfound) { step++; break; }
        }

        // final progress publish (guarantees other CTAs' t_stop spin terminates)
        if (lane == 0) {
            __threadfence();
            *((volatile uint*)&d_prog[b]) = (uint)step;
        }

        // ---- resolve global t_stop ----
        int ts = tfound;
        if (ts < 0) {
            while (true) {
                uint pv = (lane < BB) ? *((volatile uint*)&d_prog[lane]) : 0xffffffffu;
                uint mn = rmin(pv);
                bool fnd = false;
                while (scanpos < (int)mn) {
                    int idx = scanpos + lane;
                    uint mv = (idx < (int)mn) ? *((volatile uint*)&d_mask[idx]) : 0u;
                    uint bal = __ballot_sync(0xffffffffu, mv == FULL);
                    if (bal) { ts = scanpos + __ffs(bal) - 1; fnd = true; break; }
                    scanpos += 32; if (scanpos > (int)mn) scanpos = (int)mn;
                }
                if (fnd) break;
                if (mn >= (uint)STEPS) { ts = STEPS - 1; break; }
            }
        }
        if (lane == 0) s_misc[1] = ts;
    }
    __syncthreads();   // idle warps sleep here during the loop

    // ================= finalize (all 512 threads, SMEM logs) =================
    uint*          pm   = (uint*)(smraw + OFF_GPAIR);            // overlay, 16KB
    unsigned char* hist = (unsigned char*)(smraw + OFF_GPAIR + 16384);
    unsigned char* path = (unsigned char*)(smraw + OFF_GPAIR + 20480);

    for (int c = tid; c < HW; c += 512) { pm[c] = 0u; hist[c] = 0; path[c] = 0; }
    __syncthreads();

    const int ts = s_misc[1];
    for (int s = tid; s <= ts; s += 512) {
        int sl = s_sellog[s];
        hist[sl] = 1;
        int cnt = s_updcnt[s];
        uint packed = ((uint)(s + 1) << 12) | (uint)sl;          // last-writer wins
        for (int k = 0; k < cnt; k++)
            atomicMax(&pm[s_updcel[s * 8 + k]], packed);
    }
    __syncthreads();

    if (tid == 0) {
        path[goalIdx] = 1;
        uint pv = pm[goalIdx];
        int loc = pv ? (int)(pv & 4095u) : goalIdx;
        for (int i = 0; i < ts; i++) {
            if (path[loc]) break;    // deterministic chase: revisit => future marks redundant
            path[loc] = 1;
            uint q = pm[loc];
            loc = q ? (int)(q & 4095u) : goalIdx;
        }
    }
    __syncthreads();

    for (int c = tid; c < HW; c += 512) {
        out[b * HW + c]           = hist[c] ? 1.0f : 0.0f;   // hist (B,1,64,64)
        out[BB * HW + b * HW + c] = path[c] ? 1.0f : 0.0f;   // path_maps (B,1,64,64)
    }
}

// ---------------- launch -------------------------------------------------
extern "C" void kernel_launch(void* const* d_in, const int* in_sizes, int n_in,
                              void* d_out, int out_size) {
    const float* cost  = (const float*)d_in[0];
    const float* start = (const float*)d_in[1];
    const float* goal  = (const float*)d_in[2];
    const float* obst  = (const float*)d_in[3];
    float* out = (float*)d_out;

    cudaFuncSetAttribute(astar_fused, cudaFuncAttributeMaxDynamicSharedMemorySize, SMEM_TOTAL);
    astar_fused<<<BB, 512, SMEM_TOTAL>>>(cost, start, goal, obst, out);
}

// round 7
// speedup vs baseline: 2.3139x; 1.6828x over previous
#include <cuda_runtime.h>

#define HW    4096
#define BB    16
#define STEPS 409   // int(0.1 * 64 * 64)

typedef unsigned long long ull;
typedef unsigned int uint;

#define SENT 0xFFFFFFFFFFFFFFFFull
#define FINF __int_as_float(0x7F800000)

// cross-CTA coordination (zeroed in-kernel via generation handshake)
__device__ uint d_mask[STEPS];   // per-step solved bitmask across batches
__device__ uint d_prog[BB];      // per-batch completed-step counter
__device__ uint d_ready;         // monotone generation counter across launches

__device__ __forceinline__ uint rmin(uint v){uint d;asm volatile("redux.sync.min.u32 %0, %1, 0xffffffff;":"=r"(d):"r"(v):"memory");return d;}

__device__ __forceinline__ ull packf(float f, int idx){
    return ((ull)__float_as_uint(f) << 32) | (ull)(uint)idx;
}
__device__ __forceinline__ ull umin64(ull a, ull b){ return a < b ? a : b; }

// ---- predicated ops (0-BSSY; ptxas won't emit these from C++ if{}) ----
__device__ __forceinline__ void stp_f32(bool p, uint a, float v){
    asm volatile("{.reg .pred q; setp.ne.u32 q,%0,0; @q st.shared.f32 [%1],%2;}"
        ::"r"((uint)p),"r"(a),"f"(v):"memory");
}
__device__ __forceinline__ void stp_u32(bool p, uint a, uint v){
    asm volatile("{.reg .pred q; setp.ne.u32 q,%0,0; @q st.shared.u32 [%1],%2;}"
        ::"r"((uint)p),"r"(a),"r"(v):"memory");
}
__device__ __forceinline__ void redp_or(bool p, uint* a, uint v){
    asm volatile("{.reg .pred q; setp.ne.u32 q,%0,0; @q red.global.or.b32 [%1],%2;}"
        ::"r"((uint)p),"l"(a),"r"(v):"memory");
}
__device__ __forceinline__ void stp_g_u32(bool p, uint* a, uint v){
    asm volatile("{.reg .pred q; setp.ne.u32 q,%0,0; @q st.volatile.global.u32 [%1],%2;}"
        ::"r"((uint)p),"l"(a),"r"(v):"memory");
}

// ---- dynamic SMEM layout (bytes) ----
#define OFF_F      0        // float[4096]: f = 0.5g+0.5(h+cost); +INF when not open
#define OFF_GPAIR  16384    // float2[4096] {g, cost}; overlaid by pm/hist/path in finalize
#define OFF_HC     49152    // float[4096] heuristic+cost
#define OFF_STATE  65536    // uint[4096] bit0 open, bit1 closed, bit2 free
#define OFF_ROWP   81920    // ull[64] per-row packed min (init handoff)
#define OFF_SELLOG 82432    // uint[512]
#define OFF_UPDCNT 84480    // uint[512]
#define OFF_UPDCEL 86528    // uint[512*8]
#define OFF_MISC   102912   // int[0]=goal, int[1]=t_stop
#define SMEM_TOTAL 102928

__global__ void __launch_bounds__(512, 1)
astar_fused(const float* __restrict__ cost, const float* __restrict__ start,
            const float* __restrict__ goalm, const float* __restrict__ obst,
            float* __restrict__ out)
{
    extern __shared__ char smraw[];
    float*  s_f      = (float*)(smraw + OFF_F);
    float2* s_gp     = (float2*)(smraw + OFF_GPAIR);
    float*  s_hc     = (float*)(smraw + OFF_HC);
    uint*   s_state  = (uint*)(smraw + OFF_STATE);
    ull*    s_rowp   = (ull*)(smraw + OFF_ROWP);
    uint*   s_sellog = (uint*)(smraw + OFF_SELLOG);
    uint*   s_updcnt = (uint*)(smraw + OFF_UPDCNT);
    uint*   s_updcel = (uint*)(smraw + OFF_UPDCEL);
    int*    s_misc   = (int*)(smraw + OFF_MISC);

    const int b    = blockIdx.x;
    const int tid  = threadIdx.x;
    const int lane = tid & 31;
    const int warp = tid >> 5;

    const float* cb = cost  + b * HW;
    const float* sb = start + b * HW;
    const float* gb = goalm + b * HW;
    const float* ob = obst  + b * HW;

    // ---- zero this CTA's slice of coordination state + find goal ----
    {
        int s = b + tid * BB;
        if (s < STEPS) d_mask[s] = 0u;
        if (tid == 0) d_prog[b] = 0u;
    }
    {   // vectorized goal scan (one-hot)
        const float4* g4 = (const float4*)gb;
        for (int c = tid; c < HW / 4; c += 512) {
            float4 v = g4[c];
            if (v.x > 0.5f) s_misc[0] = 4 * c + 0;
            if (v.y > 0.5f) s_misc[0] = 4 * c + 1;
            if (v.z > 0.5f) s_misc[0] = 4 * c + 2;
            if (v.w > 0.5f) s_misc[0] = 4 * c + 3;
        }
    }
    __threadfence();
    __syncthreads();
    if (tid == 0) {
        uint old = atomicAdd(&d_ready, 1u);
        uint target = ((old >> 4) + 1u) << 4;   // 16 CTAs per run-generation
        while (*((volatile uint*)&d_ready) < target) {}
        __threadfence();
    }
    __syncthreads();

    const int goalIdx = s_misc[0];
    const int grow = goalIdx >> 6, gcol = goalIdx & 63;

    // ---- per-cell init ----
    for (int c = tid; c < HW; c += 512) {
        int r = c >> 6, col = c & 63;
        int di = abs(r - grow), dj = abs(col - gcol);
        int cheb = (di > dj) ? di : dj;                 // sum - min = max
        float euc = sqrtf((float)(di * di + dj * dj));
        float h = __fadd_rn((float)cheb, __fmul_rn(0.001f, euc));
        float cc = cb[c];
        h = __fadd_rn(h, cc);                            // h_total = heuristic + cost
        s_hc[c] = h;
        s_gp[c] = make_float2(0.0f, cc);
        uint st = 0;
        if (ob[c] > 0.5f) st |= 4u;
        bool open = (sb[c] > 0.5f);
        if (open) st |= 1u;
        s_state[c] = st;
        s_f[c] = open ? __fmul_rn(0.5f, h) : FINF;       // f = 0.5*0 + 0.5*h
    }
    __syncthreads();

    // ---- build per-row packed minima (16 warps x 4 rows) ----
    for (int k = 0; k < 4; k++) {
        int r = (warp << 2) + k, base = r << 6;
        ull q0 = packf(s_f[base + lane], base + lane);
        ull q1 = packf(s_f[base + 32 + lane], base + 32 + lane);
        ull q = umin64(q0, q1);
        uint hi = (uint)(q >> 32), M = rmin(hi);
        uint lo = (hi == M) ? (uint)q : 0xFFFFFFFFu, L = rmin(lo);
        if (lane == 0) s_rowp[r] = ((ull)M << 32) | L;
    }
    __syncthreads();

    // ================= single-warp driver loop (branchless body) =================
    if (warp == 0) {
        const uint FULL = (1u << BB) - 1u;
        const bool lane0 = (lane == 0);
        const uint fB  = (uint)__cvta_generic_to_shared(s_f);
        const uint gpB = (uint)__cvta_generic_to_shared(s_gp);
        const uint stB = (uint)__cvta_generic_to_shared(s_state);
        const uint slB = (uint)__cvta_generic_to_shared(s_sellog);
        const uint ucB = (uint)__cvta_generic_to_shared(s_updcnt);
        const uint ueB = (uint)__cvta_generic_to_shared(s_updcel);

        // lane l owns rows l (rpA) and l+32 (rpB)
        ull rpA = s_rowp[lane], rpB = s_rowp[lane + 32];

        int tfound = -1, scanpos = 0, step;
        uint pv_pref = 0xffffffffu, mv_pref = 0u;

        for (step = 0; step < STEPS; ++step) {
            // ---- global argmin from register row minima (tie: smallest idx) ----
            ull p = umin64(rpA, rpB);
            uint hi = (uint)(p >> 32);
            uint M = rmin(hi);
            uint lo = (hi == M) ? (uint)p : 0xFFFFFFFFu;
            uint L = rmin(lo);
            const int sel  = (int)(L & 0xFFFFu);
            const int srow = sel >> 6, scol = sel & 63, rb = srow << 6;
            const bool solved = (sel == goalIdx);

            float2 gp = s_gp[sel];
            float g2 = __fadd_rn(gp.x, gp.y);           // g[sel] + cost[sel]
            float k0 = s_f[rb + lane];                  // pre-update row snapshot
            float k1 = s_f[rb + 32 + lane];
            uint stSel = s_state[sel];

            // ---- neighbor evaluation: all 32 lanes, no branches ----
            int nidx = lane + (lane >= 4 ? 1 : 0);      // skip center (valid for lane<8)
            int ni = srow + nidx / 3 - 1;
            int nj = scol + nidx % 3 - 1;
            bool inb = (lane < 8) & ((uint)ni < 64u) & ((uint)nj < 64u);
            int nbi = inb ? ((ni << 6) | nj) : sel;     // safe dummy index
            uint stN  = s_state[nbi];
            float gn  = s_gp[nbi].x;
            float hcN = s_hc[nbi];
            bool fre  = (stN & 4u) != 0u;
            bool opn  = (stN & 1u) != 0u;
            bool cls  = (stN & 2u) != 0u;
            bool upd  = inb & fre & ((!opn & !cls) | (opn & (gn > g2)));
            float nf  = __fmul_rn(0.5f, __fadd_rn(g2, hcN));   // 0.5*g2 + 0.5*h
            ull npack = upd ? packf(nf, nbi) : SENT;

            uint m8 = __ballot_sync(0xffffffffu, upd);  // convergence: snapshot reads done
            ull n0 = __shfl_sync(0xffffffffu, npack, 0);
            ull n1 = __shfl_sync(0xffffffffu, npack, 1);
            ull n2 = __shfl_sync(0xffffffffu, npack, 2);
            ull pL = __shfl_sync(0xffffffffu, npack, 3);
            ull pR = __shfl_sync(0xffffffffu, npack, 4);
            ull n5 = __shfl_sync(0xffffffffu, npack, 5);
            ull n6 = __shfl_sync(0xffffffffu, npack, 6);
            ull n7 = __shfl_sync(0xffffffffu, npack, 7);
            ull up1  = umin64(umin64(n0, n1), n2);      // row srow-1 decrease
            ull mid1 = umin64(pL, pR);                  // row srow   decrease
            ull dn1  = umin64(umin64(n5, n6), n7);      // row srow+1 decrease

            // ---- removal rescan (always executed; selected by `solved` later) ----
            ull p0 = packf(k0, rb + lane);
            ull p1 = packf(k1, rb + 32 + lane);
            p0 = ((scol < 32) & (lane == scol))        ? SENT : p0;
            p1 = ((scol >= 32) & (lane == scol - 32))  ? SENT : p1;
            {   // same-row substitutions (pL/pR are SENT when absent -> umin no-op)
                int cL = scol - 1, cR = scol + 1;
                p0 = ((cL >= 0) & (cL < 32) & (lane == cL))       ? umin64(p0, pL) : p0;
                p1 = ((cL >= 32) & (lane == cL - 32))             ? umin64(p1, pL) : p1;
                p0 = ((cR < 32) & (lane == cR))                   ? umin64(p0, pR) : p0;
                p1 = ((cR >= 32) & (cR < 64) & (lane == cR - 32)) ? umin64(p1, pR) : p1;
            }
            ull pp = umin64(p0, p1);
            uint h2 = (uint)(pp >> 32);
            uint mm = rmin(h2);
            uint l2 = (h2 == mm) ? (uint)pp : 0xFFFFFFFFu;
            uint lm2 = rmin(l2);
            ull newrow_uns = ((ull)mm << 32) | lm2;

            ull curA = __shfl_sync(0xffffffffu, rpA, srow & 31);
            ull curB = __shfl_sync(0xffffffffu, rpB, srow & 31);
            ull cur  = (srow < 32) ? curA : curB;
            ull newrow = solved ? umin64(cur, mid1) : newrow_uns;

            // ---- merge updated rows into register row minima (SELs) ----
            rpA = ((srow < 32) & (lane == srow))        ? newrow : rpA;
            rpB = ((srow >= 32) & (lane == srow - 32))  ? newrow : rpB;
            {
                int rU = srow - 1, rD = srow + 1;
                rpA = ((rU >= 0) & (rU < 32) & (lane == rU))        ? umin64(rpA, up1) : rpA;
                rpB = ((rU >= 32) & (lane == rU - 32))              ? umin64(rpB, up1) : rpB;
                rpA = ((rD < 32) & (lane == rD))                    ? umin64(rpA, dn1) : rpA;
                rpB = ((rD >= 32) & (rD < 64) & (lane == rD - 32))  ? umin64(rpB, dn1) : rpB;
            }

            // ---- predicated SMEM/global writes (0-BSSY) ----
            int pos = __popc(m8 & ((1u << lane) - 1u));
            stp_f32(upd, fB + (uint)nbi * 4u, nf);
            stp_f32(upd, gpB + (uint)nbi * 8u, g2);
            stp_u32(upd, stB + (uint)nbi * 4u, stN | 1u);
            stp_u32(upd, ueB + (uint)(step * 8 + pos) * 4u, (uint)nbi);

            uint newStSel = solved ? (stSel | 2u) : ((stSel & ~1u) | 2u);
            stp_f32(lane0 & !solved, fB + (uint)sel * 4u, FINF);
            stp_u32(lane0, stB + (uint)sel * 4u, newStSel);
            stp_u32(lane0, slB + (uint)step * 4u, (uint)sel);
            stp_u32(lane0, ucB + (uint)step * 4u, (uint)__popc(m8));
            redp_or(lane0 & solved, &d_mask[step], 1u << b);

            // ---- periodic progress publish + prefetched t_stop detection ----
            if ((step & 7) == 7) {                      // warp-uniform branch
                __threadfence();
                stp_g_u32(lane0, &d_prog[b], (uint)(step + 1));
            }
            if (((step & 15) == 14) && tfound < 0) {
                pv_pref = (lane < BB) ? *((volatile uint*)&d_prog[lane]) : 0xffffffffu;
                int idx = scanpos + lane;
                mv_pref = (idx < STEPS) ? *((volatile uint*)&d_mask[idx]) : 0u;
            }
            if (((step & 15) == 15) && tfound < 0) {
                uint mn = rmin(pv_pref);
                bool first = true;
                while (scanpos < (int)mn) {
                    int idx = scanpos + lane;
                    uint mv;
                    if (first) { mv = (idx < (int)mn) ? mv_pref : 0u; first = false; }
                    else       { mv = (idx < (int)mn) ? *((volatile uint*)&d_mask[idx]) : 0u; }
                    uint bal = __ballot_sync(0xffffffffu, mv == FULL);
                    if (bal) { tfound = scanpos + __ffs(bal) - 1; break; }
                    scanpos += 32; if (scanpos > (int)mn) scanpos = (int)mn;
                }
            }
            if (tfound >= 0 && step >= tfound) { step++; break; }
        }

        // final progress publish (guarantees other CTAs' t_stop spin terminates)
        if (lane == 0) {
            __threadfence();
            *((volatile uint*)&d_prog[b]) = (uint)step;
        }

        // ---- resolve global t_stop ----
        int ts = tfound;
        if (ts < 0) {
            while (true) {
                uint pv = (lane < BB) ? *((volatile uint*)&d_prog[lane]) : 0xffffffffu;
                uint mn = rmin(pv);
                bool fnd = false;
                while (scanpos < (int)mn) {
                    int idx = scanpos + lane;
                    uint mv = (idx < (int)mn) ? *((volatile uint*)&d_mask[idx]) : 0u;
                    uint bal = __ballot_sync(0xffffffffu, mv == FULL);
                    if (bal) { ts = scanpos + __ffs(bal) - 1; fnd = true; break; }
                    scanpos += 32; if (scanpos > (int)mn) scanpos = (int)mn;
                }
                if (fnd) break;
                if (mn >= (uint)STEPS) { ts = STEPS - 1; break; }
            }
        }
        if (lane == 0) s_misc[1] = ts;
    }
    __syncthreads();   // idle warps sleep here during the loop

    // ================= finalize (all 512 threads, SMEM logs) =================
    uint*          pm   = (uint*)(smraw + OFF_GPAIR);            // overlay, 16KB
    unsigned char* hist = (unsigned char*)(smraw + OFF_GPAIR + 16384);
    unsigned char* path = (unsigned char*)(smraw + OFF_GPAIR + 20480);

    for (int c = tid; c < HW; c += 512) { pm[c] = 0u; hist[c] = 0; path[c] = 0; }
    __syncthreads();

    const int ts = s_misc[1];
    for (int s = tid; s <= ts; s += 512) {
        int sl = (int)s_sellog[s];
        hist[sl] = 1;
        int cnt = (int)s_updcnt[s];
        uint packed = ((uint)(s + 1) << 12) | (uint)sl;          // last-writer wins
        for (int k = 0; k < cnt; k++)
            atomicMax(&pm[s_updcel[s * 8 + k]], packed);
    }
    __syncthreads();

    if (tid == 0) {
        path[goalIdx] = 1;
        uint pv = pm[goalIdx];
        int loc = pv ? (int)(pv & 4095u) : goalIdx;
        for (int i = 0; i < ts; i++) {
            if (path[loc]) break;    // deterministic chase: revisit => future marks redundant
            path[loc] = 1;
            uint q = pm[loc];
            loc = q ? (int)(q & 4095u) : goalIdx;
        }
    }
    __syncthreads();

    for (int c = tid; c < HW; c += 512) {
        out[b * HW + c]           = hist[c] ? 1.0f : 0.0f;   // hist (B,1,64,64)
        out[BB * HW + b * HW + c] = path[c] ? 1.0f : 0.0f;   // path_maps (B,1,64,64)
    }
}

// ---------------- launch -------------------------------------------------
extern "C" void kernel_launch(void* const* d_in, const int* in_sizes, int n_in,
                              void* d_out, int out_size) {
    const float* cost  = (const float*)d_in[0];
    const float* start = (const float*)d_in[1];
    const float* goal  = (const float*)d_in[2];
    const float* obst  = (const float*)d_in[3];
    float* out = (float*)d_out;

    cudaFuncSetAttribute(astar_fused, cudaFuncAttributeMaxDynamicSharedMemorySize, SMEM_TOTAL);
    astar_fused<<<BB, 512, SMEM_TOTAL>>>(cost, start, goal, obst, out);
}